// round 15
// baseline (speedup 1.0000x reference)
#include <cuda_runtime.h>
#include <cuda_bf16.h>

// ---------------------------------------------------------------------------
// Weight_Generation: conv3x3(3->16) + BatchNorm(train) + ReLU on [1024,3,32,32]
// plus hypernetwork generating 36 conv weight tensors from 242 z-vectors.
// Output layout (float32): [ 36 weight tensors = 242*2304 floats ][ y ]
//
// Conv mapping (R15): 4096 blocks = 4 x 8-row tiles per image.
//   warp = channel pair (8 warps = 16 ch); lane = (row, col-octet);
//   thread = 8 adjacent pixels x 2 packed channels.
//   -> 27 LDC.64 / thread (was 216): removes the constant-port bottleneck.
// ---------------------------------------------------------------------------

#define Y_OFFSET   (242 * 2304)
#define N_ELEM_PER_CH (1024.0f * 1024.0f)
#define N_CONV_BLOCKS 4096               // 4 blocks per image (8 rows each)

typedef unsigned long long ull;

__device__ float g_partials[N_CONV_BLOCKS * 32];
__device__ float g_scale[16];
__device__ float g_shift[16];
__device__ ull   g_stage[224];
__device__ int   g_count = 0;

// conv weight pairs (216) + bias pairs (8)
__constant__ ull c_wb[224];

__constant__ int c_offs[37] = {
    0,1,2,3,4,5,6,7,8,9,10,11,12,
    14,
    18,22,26,30,34,38,42,46,50,54,58,
    66,
    82,98,114,130,146,162,178,194,210,226,242
};
__constant__ int c_in[36] = {
    1,1,1,1,1,1,1,1,1,1,1,1,
    1,
    2,2,2,2,2,2,2,2,2,2,2,
    2,
    4,4,4,4,4,4,4,4,4,4,4
};

// ---- packed f32x2 helpers --------------------------------------------------
__device__ __forceinline__ ull pack2(float lo, float hi) {
    ull r; asm("mov.b64 %0, {%1, %2};" : "=l"(r) : "f"(lo), "f"(hi)); return r;
}
__device__ __forceinline__ void unpack2(ull v, float& lo, float& hi) {
    asm("mov.b64 {%0, %1}, %2;" : "=f"(lo), "=f"(hi) : "l"(v));
}
__device__ __forceinline__ ull fma2(ull a, ull b, ull c) {
    ull d; asm("fma.rn.f32x2 %0, %1, %2, %3;" : "=l"(d) : "l"(a), "l"(b), "l"(c)); return d;
}
__device__ __forceinline__ ull add2(ull a, ull b) {
    ull d; asm("add.rn.f32x2 %0, %1, %2;" : "=l"(d) : "l"(a), "l"(b)); return d;
}

// ---------------------------------------------------------------------------
__global__ void prep_kernel(const float* __restrict__ cw, const float* __restrict__ cb)
{
    int t = threadIdx.x;
    if (t < 216) {
        int it = t >> 3, j = t & 7;
        int c = it / 9, r9 = it % 9, ky = r9 / 3, kx = r9 % 3;
        int o0 = 2 * j;
        g_stage[t] = pack2(cw[((o0 * 3 + c) * 3 + ky) * 3 + kx],
                           cw[(((o0 + 1) * 3 + c) * 3 + ky) * 3 + kx]);
    } else if (t < 224) {
        int j = t - 216;
        g_stage[t] = pack2(cb[2 * j], cb[2 * j + 1]);
    }
}

// ---------------------------------------------------------------------------
// Fused kernel: blocks [0,4096) = conv 8-row tiles; [4096,4338) = hypernet.
// Last conv block reduces partials -> g_scale/g_shift in-kernel.
// smem: sp2 = 3 x 10 x 34 ull (duplicated pairs) + red2 1024 f + flag
// ---------------------------------------------------------------------------
#define SP2_CH   340                      // 10*34 ull per channel
#define SMEM_ULL (3*SP2_CH + 512 + 1)

__global__ __launch_bounds__(256, 4) void fused_conv_hyper(
    const float* __restrict__ x, float* __restrict__ y,
    const float* __restrict__ bn_gamma, const float* __restrict__ bn_beta,
    const float* __restrict__ z_all,
    const float* __restrict__ w1, const float* __restrict__ b1,
    const float* __restrict__ w2, const float* __restrict__ b2,
    float* __restrict__ out)
{
    __shared__ __align__(16) ull smem_raw[SMEM_ULL];
    const int tid = threadIdx.x;

    if (blockIdx.x < N_CONV_BLOCKS) {
        // ================= CONV PATH =================
        ull*   sp2  = smem_raw;                        // 1020 ull
        float* red2 = (float*)(smem_raw + 3 * SP2_CH); // 1024 floats
        int*   flag = (int*)(smem_raw + 3 * SP2_CH + 512);

        const int n  = blockIdx.x >> 2;
        const int h0 = (blockIdx.x & 3) << 3;          // 0,8,16,24
        const float* xi = x + (long)n * 3072;

        // duplicated padded tile: rows h0-1..h0+8 (10), padded cols 0..33
        for (int i = tid; i < 3 * SP2_CH; i += 256) {
            int c = i / SP2_CH, r = i % SP2_CH;
            int yy = r / 34, xx = r % 34;
            int gy = h0 + yy - 1;
            float v = 0.0f;
            if (gy >= 0 && gy < 32 && xx >= 1 && xx < 33)
                v = xi[c * 1024 + gy * 32 + (xx - 1)];
            sp2[i] = pack2(v, v);
        }
        __syncthreads();

        // warp = channel pair j; lane -> (row r, col-octet q)
        const int j    = tid >> 5;           // 0..7
        const int lane = tid & 31;
        const int r    = lane & 7;           // 0..7
        const int q    = lane >> 3;          // 0..3  (cols q*8 .. q*8+7)

        ull acc[8];
        {
            const ull bias = c_wb[216 + j];
            #pragma unroll
            for (int p = 0; p < 8; p++) acc[p] = bias;
        }

        #pragma unroll
        for (int it9 = 0; it9 < 9; it9++) {   // (c, ky)
            const int c  = it9 / 3;
            const int ky = it9 % 3;
            const ull* rowp = sp2 + c * SP2_CH + (r + ky) * 34 + q * 8;
            ull win[10];
            {
                ulonglong2 t0 = *reinterpret_cast<const ulonglong2*>(rowp);
                ulonglong2 t1 = *reinterpret_cast<const ulonglong2*>(rowp + 2);
                ulonglong2 t2 = *reinterpret_cast<const ulonglong2*>(rowp + 4);
                ulonglong2 t3 = *reinterpret_cast<const ulonglong2*>(rowp + 6);
                ulonglong2 t4 = *reinterpret_cast<const ulonglong2*>(rowp + 8);
                win[0] = t0.x; win[1] = t0.y; win[2] = t1.x; win[3] = t1.y;
                win[4] = t2.x; win[5] = t2.y; win[6] = t3.x; win[7] = t3.y;
                win[8] = t4.x; win[9] = t4.y;
            }
            #pragma unroll
            for (int kx = 0; kx < 3; kx++) {
                const ull w = c_wb[(it9 * 3 + kx) * 8 + j];   // 27 LDC total
                #pragma unroll
                for (int p = 0; p < 8; p++)
                    acc[p] = fma2(win[p + kx], w, acc[p]);
            }
        }

        // epilogue: vectorized stores (8 adjacent px per channel) + stats
        float* yout = y + (long)n * 16 * 1024;
        const int row = h0 + r;
        float lo[8], hi[8];
        #pragma unroll
        for (int p = 0; p < 8; p++) unpack2(acc[p], lo[p], hi[p]);

        const int ch0 = 2 * j;
        float4* d0 = reinterpret_cast<float4*>(yout + ch0 * 1024 + row * 32 + q * 8);
        d0[0] = make_float4(lo[0], lo[1], lo[2], lo[3]);
        d0[1] = make_float4(lo[4], lo[5], lo[6], lo[7]);
        float4* d1 = reinterpret_cast<float4*>(yout + (ch0 + 1) * 1024 + row * 32 + q * 8);
        d1[0] = make_float4(hi[0], hi[1], hi[2], hi[3]);
        d1[1] = make_float4(hi[4], hi[5], hi[6], hi[7]);

        // packed per-thread sums, then 5-step warp shuffle on 4 scalars
        ull sm = acc[0], sq = fma2(acc[0], acc[0], pack2(0.0f, 0.0f));
        #pragma unroll
        for (int p = 1; p < 8; p++) {
            sm = add2(sm, acc[p]);
            sq = fma2(acc[p], acc[p], sq);
        }
        float s0, s1, q0, q1;
        unpack2(sm, s0, s1);
        unpack2(sq, q0, q1);
        #pragma unroll
        for (int sft = 16; sft > 0; sft >>= 1) {
            s0 += __shfl_down_sync(0xffffffffu, s0, sft);
            s1 += __shfl_down_sync(0xffffffffu, s1, sft);
            q0 += __shfl_down_sync(0xffffffffu, q0, sft);
            q1 += __shfl_down_sync(0xffffffffu, q1, sft);
        }
        if (lane == 0) {
            float* gp = g_partials + blockIdx.x * 32;
            gp[ch0]          = s0;
            gp[ch0 + 1]      = s1;
            gp[16 + ch0]     = q0;
            gp[16 + ch0 + 1] = q1;
        }
        __syncthreads();

        // ---- last-block global stats reduction ----
        if (tid == 0) {
            __threadfence();
            int old = atomicAdd(&g_count, 1);
            *flag = (old == N_CONV_BLOCKS - 1) ? 1 : 0;
        }
        __syncthreads();
        if (*flag) {
            __threadfence();
            const int v = tid & 31, g = tid >> 5;      // 8 groups x 512 blocks
            float t = 0.0f;
            #pragma unroll 8
            for (int b = g * 512; b < (g + 1) * 512; b++)
                t += g_partials[b * 32 + v];
            red2[g * 32 + v] = t;
            __syncthreads();
            if (tid < 32) {
                float tot = 0.0f;
                #pragma unroll
                for (int w = 0; w < 8; w++) tot += red2[w * 32 + tid];
                red2[256 + tid] = tot;
            }
            __syncthreads();
            if (tid < 16) {
                const float inv_n = 1.0f / N_ELEM_PER_CH;
                float mean = red2[256 + tid] * inv_n;
                float var  = red2[256 + 16 + tid] * inv_n - mean * mean;
                float rstd = rsqrtf(var + 1e-5f);
                float sc   = bn_gamma[tid] * rstd;
                g_scale[tid] = sc;
                g_shift[tid] = bn_beta[tid] - mean * sc;
            }
            if (tid == 0) g_count = 0;
        }
    } else {
        // ================= HYPERNET PATH =================
        float* zs = (float*)smem_raw;
        float* hs = zs + 64;
        const int n = blockIdx.x - N_CONV_BLOCKS;

        if (tid < 64) zs[tid] = z_all[n * 64 + tid];
        __syncthreads();

        for (int e = tid; e < 1024; e += 256) {
            float a = b2[e];
            #pragma unroll 16
            for (int k = 0; k < 64; k++)
                a += zs[k] * w2[k * 1024 + e];
            hs[e] = a;
        }
        __syncthreads();

        int li = 0;
        while (c_offs[li + 1] <= n) li++;
        const int r   = n - c_offs[li];
        const int inn = c_in[li];
        const int o   = r / inn;
        const int ii  = r % inn;
        const long base   = (long)c_offs[li] * 2304 + (long)o * inn * 2304 + (long)ii * 144;
        const int  stride = inn * 144;

        const int oo = tid >> 4;
        const int cbase = (tid & 15) * 9;
        float acc[9];
        #pragma unroll
        for (int j = 0; j < 9; j++) acc[j] = b1[cbase + j];
        #pragma unroll 8
        for (int d = 0; d < 64; d++) {
            float hv = hs[oo * 64 + d];
            const float* w1r = w1 + d * 144 + cbase;
            #pragma unroll
            for (int j = 0; j < 9; j++) acc[j] += hv * w1r[j];
        }
        float* op = out + base + (long)oo * stride + cbase;
        #pragma unroll
        for (int j = 0; j < 9; j++) op[j] = acc[j];
    }
}

// ---------------------------------------------------------------------------
// norm: 4 independent float4s per thread + streaming stores (R13 best)
// ---------------------------------------------------------------------------
__global__ __launch_bounds__(256) void norm_kernel(float* __restrict__ y)
{
    __shared__ float sc[16], sh[16];
    if (threadIdx.x < 16) {
        sc[threadIdx.x] = g_scale[threadIdx.x];
        sh[threadIdx.x] = g_shift[threadIdx.x];
    }
    __syncthreads();
    const long qt = (long)16 * 1024 * 1024 / 16;
    long i0 = (long)blockIdx.x * blockDim.x + threadIdx.x;
    long i1 = i0 + qt, i2 = i0 + 2 * qt, i3 = i0 + 3 * qt;
    float4* yv = reinterpret_cast<float4*>(y);

    float4 v0 = yv[i0];
    float4 v1 = yv[i1];
    float4 v2 = yv[i2];
    float4 v3 = yv[i3];

    int c0 = (int)((i0 >> 8) & 15);
    int c1 = (int)((i1 >> 8) & 15);
    int c2 = (int)((i2 >> 8) & 15);
    int c3 = (int)((i3 >> 8) & 15);
    float s0 = sc[c0], b0 = sh[c0];
    float s1 = sc[c1], b1 = sh[c1];
    float s2 = sc[c2], b2 = sh[c2];
    float s3 = sc[c3], b3 = sh[c3];

    v0.x = fmaxf(v0.x * s0 + b0, 0.0f); v0.y = fmaxf(v0.y * s0 + b0, 0.0f);
    v0.z = fmaxf(v0.z * s0 + b0, 0.0f); v0.w = fmaxf(v0.w * s0 + b0, 0.0f);
    v1.x = fmaxf(v1.x * s1 + b1, 0.0f); v1.y = fmaxf(v1.y * s1 + b1, 0.0f);
    v1.z = fmaxf(v1.z * s1 + b1, 0.0f); v1.w = fmaxf(v1.w * s1 + b1, 0.0f);
    v2.x = fmaxf(v2.x * s2 + b2, 0.0f); v2.y = fmaxf(v2.y * s2 + b2, 0.0f);
    v2.z = fmaxf(v2.z * s2 + b2, 0.0f); v2.w = fmaxf(v2.w * s2 + b2, 0.0f);
    v3.x = fmaxf(v3.x * s3 + b3, 0.0f); v3.y = fmaxf(v3.y * s3 + b3, 0.0f);
    v3.z = fmaxf(v3.z * s3 + b3, 0.0f); v3.w = fmaxf(v3.w * s3 + b3, 0.0f);

    __stcs(&yv[i0], v0);
    __stcs(&yv[i1], v1);
    __stcs(&yv[i2], v2);
    __stcs(&yv[i3], v3);
}

// ---------------------------------------------------------------------------
extern "C" void kernel_launch(void* const* d_in, const int* in_sizes, int n_in,
                              void* d_out, int out_size)
{
    const float* x        = (const float*)d_in[0];
    const float* conv_w   = (const float*)d_in[1];
    const float* conv_b   = (const float*)d_in[2];
    const float* bn_gamma = (const float*)d_in[3];
    const float* bn_beta  = (const float*)d_in[4];
    const float* z_all    = (const float*)d_in[5];
    const float* w1       = (const float*)d_in[6];
    const float* b1       = (const float*)d_in[7];
    const float* w2       = (const float*)d_in[8];
    const float* b2       = (const float*)d_in[9];

    float* out = (float*)d_out;
    float* y   = out + Y_OFFSET;

    prep_kernel<<<1, 224>>>(conv_w, conv_b);
    void* stage_addr = nullptr;
    cudaGetSymbolAddress(&stage_addr, g_stage);
    cudaMemcpyToSymbolAsync(c_wb, stage_addr, 224 * sizeof(ull), 0,
                            cudaMemcpyDeviceToDevice, 0);

    fused_conv_hyper<<<N_CONV_BLOCKS + 242, 256>>>(x, y, bn_gamma, bn_beta,
                                                   z_all, w1, b1, w2, b2, out);
    norm_kernel<<<4096, 256>>>(y);
}

// round 17
// speedup vs baseline: 1.2361x; 1.2361x over previous
#include <cuda_runtime.h>
#include <cuda_bf16.h>

// ---------------------------------------------------------------------------
// Weight_Generation: conv3x3(3->16) + BatchNorm(train) + ReLU on [1024,3,32,32]
// plus hypernetwork generating 36 conv weight tensors from 242 z-vectors.
// Output layout (float32): [ 36 weight tensors = 242*2304 floats ][ y ]
//
// R17 = R16 with the smem-size bug fixed (red2 needs 1024 floats = 512 ull).
// Conv weights staged in SMEM (broadcast LDS.128) instead of __constant__
// (LDC rt=8 was the over-subscribed port per R14 profile). No memcpyToSymbol.
// ---------------------------------------------------------------------------

#define Y_OFFSET   (242 * 2304)
#define N_ELEM_PER_CH (1024.0f * 1024.0f)
#define N_CONV_BLOCKS 2048               // 2 blocks per image (16 rows each)

typedef unsigned long long ull;

__device__ float g_partials[N_CONV_BLOCKS * 32];
__device__ float g_scale[16];
__device__ float g_shift[16];
__device__ ull   g_stage[224];           // packed weight pairs (216) + bias (8)
__device__ int   g_count = 0;

__constant__ int c_offs[37] = {
    0,1,2,3,4,5,6,7,8,9,10,11,12,
    14,
    18,22,26,30,34,38,42,46,50,54,58,
    66,
    82,98,114,130,146,162,178,194,210,226,242
};
__constant__ int c_in[36] = {
    1,1,1,1,1,1,1,1,1,1,1,1,
    1,
    2,2,2,2,2,2,2,2,2,2,2,
    2,
    4,4,4,4,4,4,4,4,4,4,4
};

// ---- packed f32x2 helpers --------------------------------------------------
__device__ __forceinline__ ull pack2(float lo, float hi) {
    ull r; asm("mov.b64 %0, {%1, %2};" : "=l"(r) : "f"(lo), "f"(hi)); return r;
}
__device__ __forceinline__ void unpack2(ull v, float& lo, float& hi) {
    asm("mov.b64 {%0, %1}, %2;" : "=f"(lo), "=f"(hi) : "l"(v));
}
__device__ __forceinline__ ull fma2(ull a, ull b, ull c) {
    ull d; asm("fma.rn.f32x2 %0, %1, %2, %3;" : "=l"(d) : "l"(a), "l"(b), "l"(c)); return d;
}
__device__ __forceinline__ ull add2(ull a, ull b) {
    ull d; asm("add.rn.f32x2 %0, %1, %2;" : "=l"(d) : "l"(a), "l"(b)); return d;
}

// ---------------------------------------------------------------------------
__global__ void prep_kernel(const float* __restrict__ cw, const float* __restrict__ cb)
{
    int t = threadIdx.x;
    if (t < 216) {
        int it = t >> 3, j = t & 7;
        int c = it / 9, r9 = it % 9, ky = r9 / 3, kx = r9 % 3;
        int o0 = 2 * j;
        g_stage[t] = pack2(cw[((o0 * 3 + c) * 3 + ky) * 3 + kx],
                           cw[(((o0 + 1) * 3 + c) * 3 + ky) * 3 + kx]);
    } else if (t < 224) {
        int j = t - 216;
        g_stage[t] = pack2(cb[2 * j], cb[2 * j + 1]);
    }
}

// ---------------------------------------------------------------------------
// Fused kernel: blocks [0,2048) = conv half-image tiles; [2048,2290) = hypernet.
// smem: sp2 (1836 ull) + wsm (224 ull) + red2 (512 ull = 1024 f) + flag
// ---------------------------------------------------------------------------
#define SP2_CH   612                      // 18*34 ull per channel
#define WSM_OFF  (3*SP2_CH)               // 1836
#define RED_OFF  (WSM_OFF + 224)          // 2060
#define SMEM_ULL (RED_OFF + 512 + 1)      // red2 = 1024 floats (FIX)

__global__ __launch_bounds__(256, 5) void fused_conv_hyper(
    const float* __restrict__ x, float* __restrict__ y,
    const float* __restrict__ bn_gamma, const float* __restrict__ bn_beta,
    const float* __restrict__ z_all,
    const float* __restrict__ w1, const float* __restrict__ b1,
    const float* __restrict__ w2, const float* __restrict__ b2,
    float* __restrict__ out)
{
    __shared__ __align__(16) ull smem_raw[SMEM_ULL];
    const int tid = threadIdx.x;

    if (blockIdx.x < N_CONV_BLOCKS) {
        // ================= CONV PATH =================
        ull*   sp2  = smem_raw;                        // 3*612
        ull*   wsm  = smem_raw + WSM_OFF;              // 224
        float* red2 = (float*)(smem_raw + RED_OFF);    // 1024 floats
        int*   flag = (int*)(smem_raw + RED_OFF + 512);

        const int n  = blockIdx.x >> 1;
        const int h0 = (blockIdx.x & 1) << 4;          // 0 or 16
        const float* xi = x + (long)n * 3072;

        // stage weights + bias into smem (global -> smem, L2-hit)
        if (tid < 224) wsm[tid] = g_stage[tid];

        // duplicated padded tile: rows h0-1..h0+16, padded cols 0..33
        for (int i = tid; i < 3 * SP2_CH; i += 256) {
            int c = i / SP2_CH, r = i % SP2_CH;
            int yy = r / 34, xx = r % 34;
            int gy = h0 + yy - 1;
            float v = 0.0f;
            if (gy >= 0 && gy < 32 && xx >= 1 && xx < 33)
                v = xi[c * 1024 + gy * 32 + (xx - 1)];
            sp2[i] = pack2(v, v);
        }
        __syncthreads();

        // thread -> row lr (0..15), horizontally adjacent column pair
        const int lr = tid >> 4;
        const int pc0 = (tid & 15) * 2;

        ull acc0[8], acc1[8];
        {
            ulonglong2 b0 = *reinterpret_cast<const ulonglong2*>(wsm + 216);
            ulonglong2 b1p = *reinterpret_cast<const ulonglong2*>(wsm + 218);
            ulonglong2 b2p = *reinterpret_cast<const ulonglong2*>(wsm + 220);
            ulonglong2 b3 = *reinterpret_cast<const ulonglong2*>(wsm + 222);
            acc0[0] = b0.x;  acc0[1] = b0.y;  acc0[2] = b1p.x; acc0[3] = b1p.y;
            acc0[4] = b2p.x; acc0[5] = b2p.y; acc0[6] = b3.x;  acc0[7] = b3.y;
            #pragma unroll
            for (int j = 0; j < 8; j++) acc1[j] = acc0[j];
        }

        #pragma unroll
        for (int c = 0; c < 3; c++) {
            #pragma unroll
            for (int ky = 0; ky < 3; ky++) {
                const ull* rowp = sp2 + c * SP2_CH + (lr + ky) * 34 + pc0;
                ull v0, v1, v2, v3;
                {
                    ulonglong2 t0 = *reinterpret_cast<const ulonglong2*>(rowp);
                    ulonglong2 t1 = *reinterpret_cast<const ulonglong2*>(rowp + 2);
                    v0 = t0.x; v1 = t0.y; v2 = t1.x; v3 = t1.y;
                }
                #pragma unroll
                for (int kx = 0; kx < 3; kx++) {
                    const ull a = (kx == 0) ? v0 : (kx == 1) ? v1 : v2;
                    const ull b = (kx == 0) ? v1 : (kx == 1) ? v2 : v3;
                    const ull* wp = wsm + (c * 9 + ky * 3 + kx) * 8;
                    // 4 broadcast LDS.128 -> 8 weight pairs
                    ulonglong2 w01 = *reinterpret_cast<const ulonglong2*>(wp);
                    ulonglong2 w23 = *reinterpret_cast<const ulonglong2*>(wp + 2);
                    ulonglong2 w45 = *reinterpret_cast<const ulonglong2*>(wp + 4);
                    ulonglong2 w67 = *reinterpret_cast<const ulonglong2*>(wp + 6);
                    ull w[8] = { w01.x, w01.y, w23.x, w23.y,
                                 w45.x, w45.y, w67.x, w67.y };
                    #pragma unroll
                    for (int j = 0; j < 8; j++) {
                        acc0[j] = fma2(a, w[j], acc0[j]);
                        acc1[j] = fma2(b, w[j], acc1[j]);
                    }
                }
            }
        }

        // epilogue: paired stores + packed stats
        float* yout = y + (long)n * 16 * 1024;
        const int pg = (h0 + lr) * 32 + pc0;
        ull sum2[8], sq2[8];
        #pragma unroll
        for (int j = 0; j < 8; j++) {
            float a0, a1, b0, b1v;
            unpack2(acc0[j], a0, a1);
            unpack2(acc1[j], b0, b1v);
            *reinterpret_cast<float2*>(yout + (2 * j) * 1024 + pg)     = make_float2(a0, b0);
            *reinterpret_cast<float2*>(yout + (2 * j + 1) * 1024 + pg) = make_float2(a1, b1v);
            sum2[j] = add2(acc0[j], acc1[j]);
            sq2[j]  = fma2(acc1[j], acc1[j], fma2(acc0[j], acc0[j], pack2(0.0f, 0.0f)));
        }

        float s[16], q[16];
        #pragma unroll
        for (int j = 0; j < 8; j++) {
            unpack2(sum2[j], s[2 * j], s[2 * j + 1]);
            unpack2(sq2[j],  q[2 * j], q[2 * j + 1]);
        }
        #pragma unroll
        for (int o = 0; o < 16; o++) {
            #pragma unroll
            for (int sft = 16; sft >= 4; sft >>= 1) {
                s[o] += __shfl_down_sync(0xffffffffu, s[o], sft);
                q[o] += __shfl_down_sync(0xffffffffu, q[o], sft);
            }
        }
        const int lane = tid & 31, wp = tid >> 5;
        if (lane < 4) {
            float* rr = red2 + (wp * 4 + lane) * 32;
            #pragma unroll
            for (int o = 0; o < 16; o++) { rr[o] = s[o]; rr[16 + o] = q[o]; }
        }
        __syncthreads();
        if (tid < 32) {
            float t = 0.0f;
            #pragma unroll
            for (int g = 0; g < 32; g++) t += red2[g * 32 + tid];
            g_partials[blockIdx.x * 32 + tid] = t;
        }
        __syncthreads();

        // ---- last-block global stats reduction (R7/R13 version) ----
        if (tid == 0) {
            __threadfence();
            int old = atomicAdd(&g_count, 1);
            *flag = (old == N_CONV_BLOCKS - 1) ? 1 : 0;
        }
        __syncthreads();
        if (*flag) {
            __threadfence();
            const int v = tid & 31, g = tid >> 5;      // 8 groups x 256 blocks
            float t = 0.0f;
            #pragma unroll 8
            for (int b = g * 256; b < (g + 1) * 256; b++)
                t += g_partials[b * 32 + v];
            red2[g * 32 + v] = t;
            __syncthreads();
            if (tid < 32) {
                float tot = 0.0f;
                #pragma unroll
                for (int w = 0; w < 8; w++) tot += red2[w * 32 + tid];
                red2[256 + tid] = tot;
            }
            __syncthreads();
            if (tid < 16) {
                const float inv_n = 1.0f / N_ELEM_PER_CH;
                float mean = red2[256 + tid] * inv_n;
                float var  = red2[256 + 16 + tid] * inv_n - mean * mean;
                float rstd = rsqrtf(var + 1e-5f);
                float sc   = bn_gamma[tid] * rstd;
                g_scale[tid] = sc;
                g_shift[tid] = bn_beta[tid] - mean * sc;
            }
            if (tid == 0) g_count = 0;
        }
    } else {
        // ================= HYPERNET PATH =================
        float* zs = (float*)smem_raw;
        float* hs = zs + 64;
        const int n = blockIdx.x - N_CONV_BLOCKS;

        if (tid < 64) zs[tid] = z_all[n * 64 + tid];
        __syncthreads();

        for (int e = tid; e < 1024; e += 256) {
            float a = b2[e];
            #pragma unroll 16
            for (int k = 0; k < 64; k++)
                a += zs[k] * w2[k * 1024 + e];
            hs[e] = a;
        }
        __syncthreads();

        int li = 0;
        while (c_offs[li + 1] <= n) li++;
        const int r   = n - c_offs[li];
        const int inn = c_in[li];
        const int o   = r / inn;
        const int ii  = r % inn;
        const long base   = (long)c_offs[li] * 2304 + (long)o * inn * 2304 + (long)ii * 144;
        const int  stride = inn * 144;

        const int oo = tid >> 4;
        const int cbase = (tid & 15) * 9;
        float acc[9];
        #pragma unroll
        for (int j = 0; j < 9; j++) acc[j] = b1[cbase + j];
        #pragma unroll 8
        for (int d = 0; d < 64; d++) {
            float hv = hs[oo * 64 + d];
            const float* w1r = w1 + d * 144 + cbase;
            #pragma unroll
            for (int j = 0; j < 9; j++) acc[j] += hv * w1r[j];
        }
        float* op = out + base + (long)oo * stride + cbase;
        #pragma unroll
        for (int j = 0; j < 9; j++) op[j] = acc[j];
    }
}

// ---------------------------------------------------------------------------
// norm: 4 independent float4s per thread + streaming stores (R13 best)
// ---------------------------------------------------------------------------
__global__ __launch_bounds__(256) void norm_kernel(float* __restrict__ y)
{
    __shared__ float sc[16], sh[16];
    if (threadIdx.x < 16) {
        sc[threadIdx.x] = g_scale[threadIdx.x];
        sh[threadIdx.x] = g_shift[threadIdx.x];
    }
    __syncthreads();
    const long qt = (long)16 * 1024 * 1024 / 16;
    long i0 = (long)blockIdx.x * blockDim.x + threadIdx.x;
    long i1 = i0 + qt, i2 = i0 + 2 * qt, i3 = i0 + 3 * qt;
    float4* yv = reinterpret_cast<float4*>(y);

    float4 v0 = yv[i0];
    float4 v1 = yv[i1];
    float4 v2 = yv[i2];
    float4 v3 = yv[i3];

    int c0 = (int)((i0 >> 8) & 15);
    int c1 = (int)((i1 >> 8) & 15);
    int c2 = (int)((i2 >> 8) & 15);
    int c3 = (int)((i3 >> 8) & 15);
    float s0 = sc[c0], b0 = sh[c0];
    float s1 = sc[c1], b1 = sh[c1];
    float s2 = sc[c2], b2 = sh[c2];
    float s3 = sc[c3], b3 = sh[c3];

    v0.x = fmaxf(v0.x * s0 + b0, 0.0f); v0.y = fmaxf(v0.y * s0 + b0, 0.0f);
    v0.z = fmaxf(v0.z * s0 + b0, 0.0f); v0.w = fmaxf(v0.w * s0 + b0, 0.0f);
    v1.x = fmaxf(v1.x * s1 + b1, 0.0f); v1.y = fmaxf(v1.y * s1 + b1, 0.0f);
    v1.z = fmaxf(v1.z * s1 + b1, 0.0f); v1.w = fmaxf(v1.w * s1 + b1, 0.0f);
    v2.x = fmaxf(v2.x * s2 + b2, 0.0f); v2.y = fmaxf(v2.y * s2 + b2, 0.0f);
    v2.z = fmaxf(v2.z * s2 + b2, 0.0f); v2.w = fmaxf(v2.w * s2 + b2, 0.0f);
    v3.x = fmaxf(v3.x * s3 + b3, 0.0f); v3.y = fmaxf(v3.y * s3 + b3, 0.0f);
    v3.z = fmaxf(v3.z * s3 + b3, 0.0f); v3.w = fmaxf(v3.w * s3 + b3, 0.0f);

    __stcs(&yv[i0], v0);
    __stcs(&yv[i1], v1);
    __stcs(&yv[i2], v2);
    __stcs(&yv[i3], v3);
}

// ---------------------------------------------------------------------------
extern "C" void kernel_launch(void* const* d_in, const int* in_sizes, int n_in,
                              void* d_out, int out_size)
{
    const float* x        = (const float*)d_in[0];
    const float* conv_w   = (const float*)d_in[1];
    const float* conv_b   = (const float*)d_in[2];
    const float* bn_gamma = (const float*)d_in[3];
    const float* bn_beta  = (const float*)d_in[4];
    const float* z_all    = (const float*)d_in[5];
    const float* w1       = (const float*)d_in[6];
    const float* b1       = (const float*)d_in[7];
    const float* w2       = (const float*)d_in[8];
    const float* b2       = (const float*)d_in[9];

    float* out = (float*)d_out;
    float* y   = out + Y_OFFSET;

    prep_kernel<<<1, 224>>>(conv_w, conv_b);
    fused_conv_hyper<<<N_CONV_BLOCKS + 242, 256>>>(x, y, bn_gamma, bn_beta,
                                                   z_all, w1, b1, w2, b2, out);
    norm_kernel<<<4096, 256>>>(y);
}